// round 5
// baseline (speedup 1.0000x reference)
#include <cuda_runtime.h>
#include <cstdint>
#include <cstddef>

#define BATCH 64
#define CIN   64
#define COUT  64
#define MODES 16
#define NRES  8192
#define CN    128   // n-chunk staged per block in fwd

// Persistent device scratch (allocation-free rule: __device__ globals)
__device__ float2 g_tw[NRES][MODES];          // (cos(2*pi*m*n/N), -sin(...)), 1 MB
__device__ float2 g_X [BATCH][CIN ][MODES];   // forward DFT result, 512 KB
__device__ float2 g_Y [BATCH][COUT][MODES];   // mixed + pre-scaled modes, 512 KB

typedef unsigned long long u64;

// ---- packed f32x2 helpers (sm_100+ PTX) ----
__device__ __forceinline__ void ffma2(u64 &d, u64 a, u64 b) {
    asm("fma.rn.f32x2 %0, %1, %2, %0;" : "+l"(d) : "l"(a), "l"(b));
}
__device__ __forceinline__ void fadd2(u64 &d, u64 a) {
    asm("add.rn.f32x2 %0, %0, %1;" : "+l"(d) : "l"(a));
}
__device__ __forceinline__ u64 pk2(float lo, float hi) {
    u64 r; asm("mov.b64 %0, {%1, %2};" : "=l"(r) : "f"(lo), "f"(hi)); return r;
}
__device__ __forceinline__ void upk2(u64 v, float &lo, float &hi) {
    asm("mov.b64 {%0, %1}, %2;" : "=f"(lo), "=f"(hi) : "l"(v));
}

// ------------------------------------------------------------------
// Kernel 1: twiddle table. theta = 2*pi*m*n/N = pi * ((m*n mod N)/(N/2)).
// Argument to sincospif is an exact dyadic rational -> ~1 ulp twiddles.
// ------------------------------------------------------------------
__global__ void tw_kernel() {
    int idx = blockIdx.x * blockDim.x + threadIdx.x;   // 131072 = 8192*16
    int n = idx >> 4, m = idx & 15;
    int r = (n * m) & (NRES - 1);
    float s, c;
    sincospif((float)r * (1.0f / (NRES / 2)), &s, &c);
    g_tw[n][m] = make_float2(c, -s);
}

// ------------------------------------------------------------------
// Kernel 2: truncated forward DFT.
// Block = (b, 32-row i-group). 512 threads = 16 warps.
// Lanes = i (via swizzled SMEM transpose of x), so twiddles are
// warp-uniform broadcast LDS. Accumulators: 16 x f32x2 = (Xr,Xi) per mode.
// Warp w covers n in [w*8, w*8+8) of each 128-n chunk; tree-reduce at end.
// ------------------------------------------------------------------
__global__ void __launch_bounds__(512) fwd_kernel(const float* __restrict__ x) {
    __shared__ __align__(16) char smbuf[32768];        // x(16K)+tw(16K); reused for reduce
    float4* xs4  = (float4*)smbuf;                     // 32 rows x 32 16B-units, swizzled
    float4* tws4 = (float4*)(smbuf + 16384);           // [128 n][16 modes] float2

    int b   = blockIdx.x >> 1;
    int i0  = (blockIdx.x & 1) << 5;
    int tid = threadIdx.x, w = tid >> 5, lane = tid & 31;
    const float* xb = x + (size_t)(b * CIN + i0) * NRES;

    u64 acc[16];
    #pragma unroll
    for (int m = 0; m < 16; ++m) acc[m] = 0ull;

    for (int ch = 0; ch < NRES / CN; ++ch) {
        int nbase = ch * CN;
        // stage x chunk [32 i][128 n], manual 16B swizzle for conflict-free column reads
        for (int f = tid; f < 1024; f += 512) {
            int row = f >> 5, c16 = f & 31;
            float4 v = *(const float4*)(xb + (size_t)row * NRES + nbase + (c16 << 2));
            xs4[(row << 5) + (c16 ^ (row & 7))] = v;
        }
        // stage twiddle chunk: contiguous 16 KB
        const float4* twg = (const float4*)(&g_tw[nbase][0]);
        for (int f = tid; f < 1024; f += 512) tws4[f] = twg[f];
        __syncthreads();

        int n0 = w << 3;
        #pragma unroll
        for (int nn = 0; nn < 8; nn += 4) {
            int n4 = n0 + nn;
            float4 xv = xs4[(lane << 5) + ((n4 >> 2) ^ (lane & 7))];   // x[i=lane][n4..n4+3]
            float xa[4] = {xv.x, xv.y, xv.z, xv.w};
            #pragma unroll
            for (int j = 0; j < 4; ++j) {
                u64 xx = pk2(xa[j], xa[j]);
                const ulonglong2* twp =
                    (const ulonglong2*)(smbuf + 16384 + ((n4 + j) << 7)); // uniform -> broadcast
                #pragma unroll
                for (int m2 = 0; m2 < 8; ++m2) {
                    ulonglong2 t = twp[m2];          // two (c,-s) pairs
                    ffma2(acc[2 * m2],     t.x, xx); // (Xr,Xi) += (c,-s)*x
                    ffma2(acc[2 * m2 + 1], t.y, xx);
                }
            }
        }
        __syncthreads();
    }

    // cross-warp tree reduction over the 16 n-partitions (layout conflict-free)
    u64* red = (u64*)smbuf;                 // [16 m][8 slots][32 lanes]
    for (int half = 8; half > 0; half >>= 1) {
        if (w >= half && w < (half << 1)) {
            int s = w - half;
            #pragma unroll
            for (int m = 0; m < 16; ++m) red[(m << 8) + (s << 5) + lane] = acc[m];
        }
        __syncthreads();
        if (w < half) {
            #pragma unroll
            for (int m = 0; m < 16; ++m) fadd2(acc[m], red[(m << 8) + (w << 5) + lane]);
        }
        __syncthreads();
    }
    if (w == 0) {
        u64* Xp = (u64*)(&g_X[b][i0 + lane][0]);
        #pragma unroll
        for (int m = 0; m < 16; ++m) Xp[m] = acc[m];
    }
}

// ------------------------------------------------------------------
// Kernel 3: complex mode mix + irfft scaling folded in.
// Block = b; thread = (o, m); W loads are fully coalesced (m fastest).
// Y stored pre-scaled: m==0 -> 1/N, m>=1 -> 2/N (DC imag killed by s=0).
// ------------------------------------------------------------------
__global__ void __launch_bounds__(1024) mix_kernel(const float* __restrict__ wr,
                                                   const float* __restrict__ wi) {
    __shared__ float2 Xs[CIN][MODES];       // 8 KB
    int b = blockIdx.x, tid = threadIdx.x;
    ((float2*)Xs)[tid] = ((const float2*)g_X)[b * (CIN * MODES) + tid];
    __syncthreads();
    int o = tid >> 4, m = tid & 15;
    float yr = 0.f, yi = 0.f;
    #pragma unroll 4
    for (int i = 0; i < CIN; ++i) {
        float2 xv = Xs[i][m];
        float a = wr[(i * COUT + o) * MODES + m];
        float c = wi[(i * COUT + o) * MODES + m];
        yr = fmaf(xv.x, a, yr); yr = fmaf(-xv.y, c, yr);
        yi = fmaf(xv.x, c, yi); yi = fmaf(xv.y, a, yi);
    }
    float sc = (m == 0 ? 1.0f : 2.0f) * (1.0f / NRES);
    g_Y[b][o][m] = make_float2(yr * sc, yi * sc);
}

// ------------------------------------------------------------------
// Kernel 4: truncated inverse.
// Block = (b, n-half). Thread owns one n: 16 twiddle f32x2 in REGISTERS,
// reused across all 64 o. Y[o][m] comes from SMEM via warp-uniform
// broadcast 16B loads. out = sum_m (Ysr*c + Ysi*(-s)) — halves summed at end.
// Stores are lane-coalesced STG.32.
// ------------------------------------------------------------------
__global__ void __launch_bounds__(512) inv_kernel(float* __restrict__ out) {
    __shared__ __align__(16) float2 Ysh[COUT][MODES];   // 8 KB
    int b = blockIdx.x >> 1;
    int tid = threadIdx.x;
    ((float2*)Ysh)[tid]       = ((const float2*)g_Y)[b * (COUT * MODES) + tid];
    ((float2*)Ysh)[tid + 512] = ((const float2*)g_Y)[b * (COUT * MODES) + tid + 512];
    __syncthreads();
    int nbase = (blockIdx.x & 1) << 12;                 // 0 or 4096
    float* ob = out + (size_t)b * COUT * NRES;

    for (int ch = 0; ch < 8; ++ch) {
        int n = nbase + (ch << 9) + tid;
        u64 tw[16];
        const ulonglong2* twp = (const ulonglong2*)(&g_tw[n][0]);
        #pragma unroll
        for (int m2 = 0; m2 < 8; ++m2) {
            ulonglong2 t = twp[m2];
            tw[2 * m2] = t.x; tw[2 * m2 + 1] = t.y;
        }
        #pragma unroll 2
        for (int o = 0; o < COUT; ++o) {
            const ulonglong2* yp = (const ulonglong2*)(&Ysh[o][0]);  // uniform -> broadcast
            u64 a0 = 0ull, a1 = 0ull;                                // two chains, lat-4 hidden
            #pragma unroll
            for (int m2 = 0; m2 < 8; ++m2) {
                ulonglong2 y = yp[m2];
                ffma2(a0, y.x, tw[2 * m2]);
                ffma2(a1, y.y, tw[2 * m2 + 1]);
            }
            float l0, h0, l1, h1;
            upk2(a0, l0, h0); upk2(a1, l1, h1);
            ob[(size_t)o * NRES + n] = (l0 + h0) + (l1 + h1);
        }
    }
}

// ------------------------------------------------------------------
extern "C" void kernel_launch(void* const* d_in, const int* in_sizes, int n_in,
                              void* d_out, int out_size) {
    (void)in_sizes; (void)n_in; (void)out_size;
    const float* x  = (const float*)d_in[0];   // [64,64,8192]
    const float* wr = (const float*)d_in[1];   // [64,64,16]
    const float* wi = (const float*)d_in[2];   // [64,64,16]
    float* out = (float*)d_out;                // [64,64,8192]

    tw_kernel <<<512, 256>>>();
    fwd_kernel<<<128, 512>>>(x);
    mix_kernel<<<64, 1024>>>(wr, wi);
    inv_kernel<<<128, 512>>>(out);
}

// round 6
// speedup vs baseline: 2.2044x; 2.2044x over previous
#include <cuda_runtime.h>
#include <cstdint>
#include <cstddef>

#define BATCH 64
#define CIN   64
#define COUT  64
#define MODES 16
#define NRES  8192
#define NH    4096   // NRES/2 — symmetry-reduced n range
#define CN    64     // n-chunk per fwd block

typedef unsigned long long u64;

// Persistent device scratch (allocation-free rule: __device__ globals)
// Twiddles for n<4096 only, modes stored EVEN/ODD-reordered:
//   slot s<8 -> m=2s (even), s>=8 -> m=2(s-8)+1 (odd). Each = (cos, -sin).
__device__ __align__(16) float2 g_tw[NH][MODES];            // 512 KB
__device__ __align__(16) float2 g_Xp[4][BATCH][CIN][MODES]; // fwd partials, 2 MB
__device__ __align__(16) float2 g_Y [BATCH][COUT][MODES];   // mixed+scaled, reordered

// ---- packed f32x2 helpers (sm_100+) ----
__device__ __forceinline__ void ffma2(u64 &d, u64 a, u64 b) {
    asm("fma.rn.f32x2 %0, %1, %2, %0;" : "+l"(d) : "l"(a), "l"(b));
}
__device__ __forceinline__ void fadd2(u64 &d, u64 a) {
    asm("add.rn.f32x2 %0, %0, %1;" : "+l"(d) : "l"(a));
}
__device__ __forceinline__ u64 pk2(float lo, float hi) {
    u64 r; asm("mov.b64 %0, {%1, %2};" : "=l"(r) : "f"(lo), "f"(hi)); return r;
}
__device__ __forceinline__ void upk2(u64 v, float &lo, float &hi) {
    asm("mov.b64 {%0, %1}, %2;" : "=f"(lo), "=f"(hi) : "l"(v));
}
__device__ __forceinline__ int mslot(int m) { return ((m & 1) << 3) | (m >> 1); }

// ------------------------------------------------------------------
// Kernel 1: twiddle table, n<4096, even/odd-reordered mode slots.
// Exact dyadic sincospif argument -> ~1 ulp.
// ------------------------------------------------------------------
__global__ void tw_kernel() {
    int idx = blockIdx.x * blockDim.x + threadIdx.x;   // 65536 = 4096*16
    int n = idx >> 4, m = idx & 15;
    int r = (n * m) & (NRES - 1);
    float s, c;
    sincospif((float)r * (1.0f / (NRES / 2)), &s, &c);
    g_tw[n][mslot(m)] = make_float2(c, -s);
}

// ------------------------------------------------------------------
// Kernel 2: symmetry-folded forward DFT.
// Grid 512 = (b:64, ihalf:2, q:4). Block 256 thr = 8 warps.
// u=x[n]+x[n+4096], v=x[n]-x[n+4096]; even modes use u, odd use v.
// Lanes = 32 i-rows; warp w covers 8 n of each 64-n chunk.
// Register-prefetch double-buffers gmem loads behind compute.
// ------------------------------------------------------------------
__global__ void __launch_bounds__(256, 2) fwd_kernel(const float* __restrict__ x) {
    __shared__ float2 uv[32][65];                 // (u,v), padded: conflict-free LDS.64
    __shared__ __align__(16) u64 tws[CN][16];     // chunk twiddles, reordered slots

    int bid = blockIdx.x;
    int b = bid >> 3, ihalf = (bid >> 2) & 1, q = bid & 3;
    int tid = threadIdx.x, w = tid >> 5, l = tid & 31;
    const float* xb = x + ((size_t)(b * CIN + ihalf * 32)) * NRES;

    u64 acc[16];
    #pragma unroll
    for (int s = 0; s < 16; ++s) acc[s] = 0ull;

    // prefetch chunk 0
    float4 A[2], B[2], T[2];
    {
        int nbase = q << 10;
        #pragma unroll
        for (int k = 0; k < 2; ++k) {
            int idx = k * 256 + tid, row = idx >> 4, c4 = idx & 15;
            const float* p = xb + (size_t)row * NRES + nbase + (c4 << 2);
            A[k] = *(const float4*)p;
            B[k] = *(const float4*)(p + NH);
            T[k] = ((const float4*)&g_tw[nbase][0])[idx];
        }
    }

    for (int ch = 0; ch < 16; ++ch) {
        // store phase: u/v + twiddles into smem
        #pragma unroll
        for (int k = 0; k < 2; ++k) {
            int idx = k * 256 + tid, row = idx >> 4, c4 = idx & 15;
            float4 a = A[k], bb = B[k];
            uv[row][(c4 << 2) + 0] = make_float2(a.x + bb.x, a.x - bb.x);
            uv[row][(c4 << 2) + 1] = make_float2(a.y + bb.y, a.y - bb.y);
            uv[row][(c4 << 2) + 2] = make_float2(a.z + bb.z, a.z - bb.z);
            uv[row][(c4 << 2) + 3] = make_float2(a.w + bb.w, a.w - bb.w);
            ((float4*)tws)[idx] = T[k];
        }
        __syncthreads();
        // prefetch next chunk (latency hidden by compute below)
        if (ch < 15) {
            int nbase = (q << 10) + ((ch + 1) << 6);
            #pragma unroll
            for (int k = 0; k < 2; ++k) {
                int idx = k * 256 + tid, row = idx >> 4, c4 = idx & 15;
                const float* p = xb + (size_t)row * NRES + nbase + (c4 << 2);
                A[k] = *(const float4*)p;
                B[k] = *(const float4*)(p + NH);
                T[k] = ((const float4*)&g_tw[nbase][0])[idx];
            }
        }
        // compute: 8 n per warp, lanes = i rows
        #pragma unroll
        for (int j = 0; j < 8; ++j) {
            int c = (w << 3) + j;
            float2 z = uv[l][c];
            u64 xu = pk2(z.x, z.x), xv = pk2(z.y, z.y);
            const ulonglong2* tp = (const ulonglong2*)&tws[c][0];
            #pragma unroll
            for (int m2 = 0; m2 < 4; ++m2) {       // even slots 0..7
                ulonglong2 t = tp[m2];
                ffma2(acc[2 * m2],     t.x, xu);
                ffma2(acc[2 * m2 + 1], t.y, xu);
            }
            #pragma unroll
            for (int m2 = 4; m2 < 8; ++m2) {       // odd slots 8..15
                ulonglong2 t = tp[m2];
                ffma2(acc[2 * m2],     t.x, xv);
                ffma2(acc[2 * m2 + 1], t.y, xv);
            }
        }
        __syncthreads();
    }

    // cross-warp tree reduction (8 warps -> warp 0); reuse uv area
    u64* red = (u64*)uv;
    for (int half = 4; half > 0; half >>= 1) {
        if (w >= half && w < (half << 1)) {
            int s = w - half;
            #pragma unroll
            for (int m = 0; m < 16; ++m) red[(((s << 4) + m) << 5) + l] = acc[m];
        }
        __syncthreads();
        if (w < half) {
            #pragma unroll
            for (int m = 0; m < 16; ++m) fadd2(acc[m], red[(((w << 4) + m) << 5) + l]);
        }
        __syncthreads();
    }
    if (w == 0) {
        u64* Xp = (u64*)&g_Xp[q][b][ihalf * 32 + l][0];
        #pragma unroll
        for (int m = 0; m < 16; ++m) Xp[m] = acc[m];
    }
}

// ------------------------------------------------------------------
// Kernel 3: sum 4 fwd partials + complex mode mix + irfft scale.
// Grid 128 = (b:64, ohalf:2), 512 thr; thread = (o_local, m).
// ------------------------------------------------------------------
__global__ void __launch_bounds__(512) mix_kernel(const float* __restrict__ wr,
                                                  const float* __restrict__ wi) {
    __shared__ __align__(16) float2 Xs[CIN][MODES];   // 8 KB, reordered slots
    int b = blockIdx.x >> 1, oh = blockIdx.x & 1;
    int tid = threadIdx.x;
    for (int t = tid; t < CIN * MODES; t += 512) {
        const float2* p0 = &((const float2*)g_Xp)[((0 * BATCH + b) * CIN * MODES) + t];
        float2 a = p0[0];
        float2 a1 = p0[1 * BATCH * CIN * MODES];
        float2 a2 = p0[2 * BATCH * CIN * MODES];
        float2 a3 = p0[3 * BATCH * CIN * MODES];
        ((float2*)Xs)[t] = make_float2(a.x + a1.x + a2.x + a3.x,
                                       a.y + a1.y + a2.y + a3.y);
    }
    __syncthreads();
    int o = (oh << 5) + (tid >> 4), m = tid & 15, s = mslot(m);
    float yr = 0.f, yi = 0.f;
    #pragma unroll 4
    for (int i = 0; i < CIN; ++i) {
        float2 xv = Xs[i][s];
        float a = wr[(i * COUT + o) * MODES + m];
        float c = wi[(i * COUT + o) * MODES + m];
        yr = fmaf(xv.x, a, yr); yr = fmaf(-xv.y, c, yr);
        yi = fmaf(xv.x, c, yi); yi = fmaf(xv.y, a, yi);
    }
    float sc = (m == 0 ? 1.0f : 2.0f) * (1.0f / NRES);
    g_Y[b][o][s] = make_float2(yr * sc, yi * sc);
}

// ------------------------------------------------------------------
// Kernel 4: symmetry-folded inverse.
// Grid 256 = (b:64, q:4) -> ALL blocks resident (2 blocks/SM via lb(512,2)).
// Thread owns one n<4096: 16 twiddle f32x2 in regs, reused over 64 o.
// E/O split -> out[n]=E+O, out[n+4096]=E-O (two outputs per inner loop).
// ------------------------------------------------------------------
__global__ void __launch_bounds__(512, 2) inv_kernel(float* __restrict__ out) {
    __shared__ __align__(16) u64 Ysh[COUT][MODES];   // 8 KB, reordered slots
    int b = blockIdx.x >> 2, q = blockIdx.x & 3;
    int tid = threadIdx.x;
    const u64* Yg = (const u64*)g_Y + (size_t)b * COUT * MODES;
    ((u64*)Ysh)[tid]       = Yg[tid];
    ((u64*)Ysh)[tid + 512] = Yg[tid + 512];
    __syncthreads();
    float* ob = out + (size_t)b * COUT * NRES;

    for (int ch = 0; ch < 2; ++ch) {
        int n = (q << 10) + (ch << 9) + tid;
        u64 tw[16];
        const ulonglong2* tp = (const ulonglong2*)&g_tw[n][0];
        #pragma unroll
        for (int m2 = 0; m2 < 8; ++m2) {
            ulonglong2 t = tp[m2];
            tw[2 * m2] = t.x; tw[2 * m2 + 1] = t.y;
        }
        #pragma unroll 2
        for (int o = 0; o < COUT; ++o) {
            const ulonglong2* yp = (const ulonglong2*)&Ysh[o][0];
            u64 aE = 0ull, aO = 0ull;            // two chains hide FFMA latency
            #pragma unroll
            for (int m2 = 0; m2 < 4; ++m2) {     // even slots
                ulonglong2 y = yp[m2];
                ffma2(aE, y.x, tw[2 * m2]);
                ffma2(aE, y.y, tw[2 * m2 + 1]);
            }
            #pragma unroll
            for (int m2 = 4; m2 < 8; ++m2) {     // odd slots
                ulonglong2 y = yp[m2];
                ffma2(aO, y.x, tw[2 * m2]);
                ffma2(aO, y.y, tw[2 * m2 + 1]);
            }
            float e0, e1, o0, o1;
            upk2(aE, e0, e1); upk2(aO, o0, o1);
            float E = e0 + e1, O = o0 + o1;
            ob[(size_t)o * NRES + n]       = E + O;
            ob[(size_t)o * NRES + n + NH]  = E - O;
        }
    }
}

// ------------------------------------------------------------------
extern "C" void kernel_launch(void* const* d_in, const int* in_sizes, int n_in,
                              void* d_out, int out_size) {
    (void)in_sizes; (void)n_in; (void)out_size;
    const float* x  = (const float*)d_in[0];   // [64,64,8192]
    const float* wr = (const float*)d_in[1];   // [64,64,16]
    const float* wi = (const float*)d_in[2];   // [64,64,16]
    float* out = (float*)d_out;                // [64,64,8192]

    tw_kernel <<<256, 256>>>();
    fwd_kernel<<<512, 256>>>(x);
    mix_kernel<<<128, 512>>>(wr, wi);
    inv_kernel<<<256, 512>>>(out);
}

// round 7
// speedup vs baseline: 2.4342x; 1.1042x over previous
#include <cuda_runtime.h>
#include <cstdint>
#include <cstddef>

#define BATCH 64
#define CIN   64
#define COUT  64
#define MODES 16
#define NRES  8192
#define NH    4096   // NRES/2 — symmetry-reduced n range
#define CN    32     // n-chunk per fwd block

typedef unsigned long long u64;

// Persistent device scratch (allocation-free rule: __device__ globals)
// Twiddles for n<4096 only, modes stored EVEN/ODD-reordered:
//   slot s<8 -> m=2s (even), s>=8 -> m=2(s-8)+1 (odd). Each = (cos, -sin).
__device__ __align__(16) float2 g_tw[NH][MODES];            // 512 KB
__device__ __align__(16) float2 g_Xp[4][BATCH][CIN][MODES]; // fwd n-quarter partials
__device__ __align__(16) float2 g_Y [BATCH][COUT][MODES];   // mixed+scaled, reordered

// ---- packed f32x2 helpers (sm_100+) ----
__device__ __forceinline__ void ffma2(u64 &d, u64 a, u64 b) {
    asm("fma.rn.f32x2 %0, %1, %2, %0;" : "+l"(d) : "l"(a), "l"(b));
}
__device__ __forceinline__ void fadd2(u64 &d, u64 a) {
    asm("add.rn.f32x2 %0, %0, %1;" : "+l"(d) : "l"(a));
}
__device__ __forceinline__ u64 pk2(float lo, float hi) {
    u64 r; asm("mov.b64 %0, {%1, %2};" : "=l"(r) : "f"(lo), "f"(hi)); return r;
}
__device__ __forceinline__ void upk2(u64 v, float &lo, float &hi) {
    asm("mov.b64 {%0, %1}, %2;" : "=f"(lo), "=f"(hi) : "l"(v));
}
__device__ __forceinline__ int mslot(int m) { return ((m & 1) << 3) | (m >> 1); }

// ------------------------------------------------------------------
// Kernel 1: twiddle table, n<4096, even/odd-reordered mode slots.
// ------------------------------------------------------------------
__global__ void tw_kernel() {
    int idx = blockIdx.x * blockDim.x + threadIdx.x;   // 65536 = 4096*16
    int n = idx >> 4, m = idx & 15;
    int r = (n * m) & (NRES - 1);
    float s, c;
    sincospif((float)r * (1.0f / (NRES / 2)), &s, &c);
    g_tw[n][mslot(m)] = make_float2(c, -s);
}

// ------------------------------------------------------------------
// Kernel 2: symmetry-folded forward DFT, 2 i-rows per lane.
// Grid 256 = (b:64, q:4). Block 256 thr = 8 warps, all 64 i per warp.
// Per n: 2 LDS.64 + 8 broadcast LDS.128 feed 32 ffma2 (was 1:2, now 1:3.2).
// ------------------------------------------------------------------
__global__ void __launch_bounds__(256, 2) fwd_kernel(const float* __restrict__ x) {
    __shared__ float2 uv[64][33];                 // (u,v), padded: 16.9 KB
    __shared__ __align__(16) u64 tws[CN][16];     // chunk twiddles, 4 KB

    int bid = blockIdx.x;
    int b = bid >> 2, q = bid & 3;
    int tid = threadIdx.x, w = tid >> 5, l = tid & 31;
    const float* xb = x + (size_t)b * CIN * NRES;

    u64 acc[32];                                  // [0..15]: i=l, [16..31]: i=l+32
    #pragma unroll
    for (int s = 0; s < 32; ++s) acc[s] = 0ull;

    // prefetch chunk 0
    float4 A[2], B[2], T;
    {
        int nbase = q << 10;
        #pragma unroll
        for (int k = 0; k < 2; ++k) {
            int idx = k * 256 + tid, row = idx >> 3, c4 = idx & 7;
            const float* p = xb + (size_t)row * NRES + nbase + (c4 << 2);
            A[k] = *(const float4*)p;
            B[k] = *(const float4*)(p + NH);
        }
        T = ((const float4*)&g_tw[nbase][0])[tid];
    }

    for (int ch = 0; ch < 32; ++ch) {
        // store phase
        #pragma unroll
        for (int k = 0; k < 2; ++k) {
            int idx = k * 256 + tid, row = idx >> 3, c4 = idx & 7;
            float4 a = A[k], bb = B[k];
            uv[row][(c4 << 2) + 0] = make_float2(a.x + bb.x, a.x - bb.x);
            uv[row][(c4 << 2) + 1] = make_float2(a.y + bb.y, a.y - bb.y);
            uv[row][(c4 << 2) + 2] = make_float2(a.z + bb.z, a.z - bb.z);
            uv[row][(c4 << 2) + 3] = make_float2(a.w + bb.w, a.w - bb.w);
        }
        ((float4*)tws)[tid] = T;
        __syncthreads();
        // prefetch next chunk
        if (ch < 31) {
            int nbase = (q << 10) + ((ch + 1) << 5);
            #pragma unroll
            for (int k = 0; k < 2; ++k) {
                int idx = k * 256 + tid, row = idx >> 3, c4 = idx & 7;
                const float* p = xb + (size_t)row * NRES + nbase + (c4 << 2);
                A[k] = *(const float4*)p;
                B[k] = *(const float4*)(p + NH);
            }
            T = ((const float4*)&g_tw[nbase][0])[tid];
        }
        // compute: warp w covers 4 n; lanes = 32 i, each lane does i and i+32
        #pragma unroll
        for (int j = 0; j < 4; ++j) {
            int c = (w << 2) + j;
            float2 z0 = uv[l][c], z1 = uv[l + 32][c];
            u64 xu0 = pk2(z0.x, z0.x), xv0 = pk2(z0.y, z0.y);
            u64 xu1 = pk2(z1.x, z1.x), xv1 = pk2(z1.y, z1.y);
            const ulonglong2* tp = (const ulonglong2*)&tws[c][0];
            #pragma unroll
            for (int m2 = 0; m2 < 4; ++m2) {       // even slots
                ulonglong2 t = tp[m2];
                ffma2(acc[2 * m2],      t.x, xu0);
                ffma2(acc[2 * m2 + 1],  t.y, xu0);
                ffma2(acc[16 + 2 * m2], t.x, xu1);
                ffma2(acc[17 + 2 * m2], t.y, xu1);
            }
            #pragma unroll
            for (int m2 = 4; m2 < 8; ++m2) {       // odd slots
                ulonglong2 t = tp[m2];
                ffma2(acc[2 * m2],      t.x, xv0);
                ffma2(acc[2 * m2 + 1],  t.y, xv0);
                ffma2(acc[16 + 2 * m2], t.x, xv1);
                ffma2(acc[17 + 2 * m2], t.y, xv1);
            }
        }
        __syncthreads();
    }

    // cross-warp tree reduction, two 16-acc phases (fits 16 KB in uv region)
    u64* red = (u64*)uv;
    for (int g = 0; g < 32; g += 16) {
        for (int half = 4; half > 0; half >>= 1) {
            if (w >= half && w < (half << 1)) {
                #pragma unroll
                for (int m = 0; m < 16; ++m)
                    red[((((w - half) << 4) + m) << 5) + l] = acc[g + m];
            }
            __syncthreads();
            if (w < half) {
                #pragma unroll
                for (int m = 0; m < 16; ++m)
                    fadd2(acc[g + m], red[(((w << 4) + m) << 5) + l]);
            }
            __syncthreads();
        }
    }
    if (w == 0) {
        u64* Xp = (u64*)&g_Xp[q][b][0][0];
        #pragma unroll
        for (int m = 0; m < 16; ++m) {
            Xp[l * 16 + m]        = acc[m];
            Xp[(l + 32) * 16 + m] = acc[16 + m];
        }
    }
}

// ------------------------------------------------------------------
// Kernel 3: sum 4 fwd partials + complex mode mix + irfft scale.
// ------------------------------------------------------------------
__global__ void __launch_bounds__(512) mix_kernel(const float* __restrict__ wr,
                                                  const float* __restrict__ wi) {
    __shared__ __align__(16) float2 Xs[CIN][MODES];   // 8 KB, reordered slots
    int b = blockIdx.x >> 1, oh = blockIdx.x & 1;
    int tid = threadIdx.x;
    for (int t = tid; t < CIN * MODES; t += 512) {
        const float2* p0 = &((const float2*)g_Xp)[(size_t)b * CIN * MODES + t];
        float2 a  = p0[0];
        float2 a1 = p0[1 * BATCH * CIN * MODES];
        float2 a2 = p0[2 * BATCH * CIN * MODES];
        float2 a3 = p0[3 * BATCH * CIN * MODES];
        ((float2*)Xs)[t] = make_float2(a.x + a1.x + a2.x + a3.x,
                                       a.y + a1.y + a2.y + a3.y);
    }
    __syncthreads();
    int o = (oh << 5) + (tid >> 4), m = tid & 15, s = mslot(m);
    float yr = 0.f, yi = 0.f;
    #pragma unroll 4
    for (int i = 0; i < CIN; ++i) {
        float2 xv = Xs[i][s];
        float a = wr[(i * COUT + o) * MODES + m];
        float c = wi[(i * COUT + o) * MODES + m];
        yr = fmaf(xv.x, a, yr); yr = fmaf(-xv.y, c, yr);
        yi = fmaf(xv.x, c, yi); yi = fmaf(xv.y, a, yi);
    }
    float sc = (m == 0 ? 1.0f : 2.0f) * (1.0f / NRES);
    g_Y[b][o][s] = make_float2(yr * sc, yi * sc);
}

// ------------------------------------------------------------------
// Kernel 4: symmetry-folded inverse, 2 n per thread.
// Grid 256 = (b:64, q:4), 256 thr, lb(256,2) -> all blocks resident.
// Two twiddle register sets; 8 Y broadcast-LDS feed 32 ffma2.
// out[n]=E+O, out[n+4096]=E-O for each of the 2 n.
// ------------------------------------------------------------------
__global__ void __launch_bounds__(256, 2) inv_kernel(float* __restrict__ out) {
    __shared__ __align__(16) u64 Ysh[COUT][MODES];   // 8 KB, reordered slots
    int b = blockIdx.x >> 2, q = blockIdx.x & 3;
    int tid = threadIdx.x;
    const u64* Yg = (const u64*)g_Y + (size_t)b * COUT * MODES;
    #pragma unroll
    for (int k = 0; k < 4; ++k) ((u64*)Ysh)[tid + k * 256] = Yg[tid + k * 256];
    __syncthreads();
    float* ob = out + (size_t)b * COUT * NRES;

    #pragma unroll
    for (int ch = 0; ch < 2; ++ch) {
        int n0 = (q << 10) + (ch << 9) + tid;        // second n = n0 + 256
        u64 twA[16], twB[16];
        {
            const ulonglong2* tp = (const ulonglong2*)&g_tw[n0][0];
            #pragma unroll
            for (int m2 = 0; m2 < 8; ++m2) {
                ulonglong2 t = tp[m2];
                twA[2 * m2] = t.x; twA[2 * m2 + 1] = t.y;
            }
            tp = (const ulonglong2*)&g_tw[n0 + 256][0];
            #pragma unroll
            for (int m2 = 0; m2 < 8; ++m2) {
                ulonglong2 t = tp[m2];
                twB[2 * m2] = t.x; twB[2 * m2 + 1] = t.y;
            }
        }
        #pragma unroll 2
        for (int o = 0; o < COUT; ++o) {
            const ulonglong2* yp = (const ulonglong2*)&Ysh[o][0];
            u64 e0 = 0ull, o0 = 0ull, e1 = 0ull, o1 = 0ull;
            #pragma unroll
            for (int m2 = 0; m2 < 4; ++m2) {         // even slots
                ulonglong2 y = yp[m2];
                ffma2(e0, y.x, twA[2 * m2]); ffma2(e0, y.y, twA[2 * m2 + 1]);
                ffma2(e1, y.x, twB[2 * m2]); ffma2(e1, y.y, twB[2 * m2 + 1]);
            }
            #pragma unroll
            for (int m2 = 4; m2 < 8; ++m2) {         // odd slots
                ulonglong2 y = yp[m2];
                ffma2(o0, y.x, twA[2 * m2]); ffma2(o0, y.y, twA[2 * m2 + 1]);
                ffma2(o1, y.x, twB[2 * m2]); ffma2(o1, y.y, twB[2 * m2 + 1]);
            }
            float lo, hi, E, O;
            float* p = ob + (size_t)o * NRES;
            upk2(e0, lo, hi); E = lo + hi;
            upk2(o0, lo, hi); O = lo + hi;
            p[n0]            = E + O;
            p[n0 + NH]       = E - O;
            upk2(e1, lo, hi); E = lo + hi;
            upk2(o1, lo, hi); O = lo + hi;
            p[n0 + 256]      = E + O;
            p[n0 + 256 + NH] = E - O;
        }
    }
}

// ------------------------------------------------------------------
extern "C" void kernel_launch(void* const* d_in, const int* in_sizes, int n_in,
                              void* d_out, int out_size) {
    (void)in_sizes; (void)n_in; (void)out_size;
    const float* x  = (const float*)d_in[0];   // [64,64,8192]
    const float* wr = (const float*)d_in[1];   // [64,64,16]
    const float* wi = (const float*)d_in[2];   // [64,64,16]
    float* out = (float*)d_out;                // [64,64,8192]

    tw_kernel <<<256, 256>>>();
    fwd_kernel<<<256, 256>>>(x);
    mix_kernel<<<128, 512>>>(wr, wi);
    inv_kernel<<<256, 256>>>(out);
}